// round 5
// baseline (speedup 1.0000x reference)
#include <cuda_runtime.h>
#include <cuda_bf16.h>
#include <math.h>

// Problem constants
#define VOCAB 50000
#define DIM   512
#define SEQL  512
#define BATCH 256
#define NCLS  20

// h staging: per-warp private buffer, 4 rows x 516 floats (pad kills bank conflicts)
#define HROW  516
#define HWARP (4 * HROW)                       // floats per warp buffer
#define RNN_SMEM_FLOATS (512 * 64 + 8 * HWARP) // Wh slice + 8 warp buffers
#define RNN_SMEM_BYTES  (RNN_SMEM_FLOATS * 4)  // 197,120 B

// ---------------- device scratch (no runtime alloc allowed) ----------------
__device__ float g_embW[(size_t)VOCAB * DIM];       // emb @ Wx + b, ~100 MB
__device__ float g_h[2 * BATCH * DIM];              // ping-pong hidden state
__device__ unsigned g_flags[16][32];                // per-CTA step counters (8 used/group)

// strong-op helpers (PTX memory model)
__device__ __forceinline__ unsigned ld_relaxed(const unsigned* p) {
    unsigned v;
    asm volatile("ld.relaxed.gpu.global.u32 %0, [%1];" : "=r"(v) : "l"(p) : "memory");
    return v;
}
__device__ __forceinline__ void red_release_add(unsigned* p, unsigned v) {
    asm volatile("red.release.gpu.global.add.u32 [%0], %1;" :: "l"(p), "r"(v) : "memory");
}
__device__ __forceinline__ void fence_acq_rel_gpu() {
    asm volatile("fence.acq_rel.gpu;" ::: "memory");
}

// ---------------- kernel 1: embW = emb @ Wx + b  (fp32 tiled GEMM) ----------
// M=50000, N=512, K=512.  BM=128, BN=64, BK=16, 256 threads, 8x4 per thread.
__global__ __launch_bounds__(256) void embw_gemm(
    const float* __restrict__ A,    // emb [M][512]
    const float* __restrict__ B,    // Wx  [512][512]
    const float* __restrict__ bias, // b [512]
    int M)
{
    __shared__ float As[16][132];   // transposed A tile [k][m], padded
    __shared__ float Bs[16][64];    // [k][n]

    const int tid  = threadIdx.x;
    const int row0 = blockIdx.y * 128;
    const int col0 = blockIdx.x * 64;

    const int tm = tid >> 4;        // 0..15 -> 8 rows each
    const int tn = tid & 15;        // 0..15 -> 4 cols each

    float4 acc[8];
    #pragma unroll
    for (int i = 0; i < 8; i++) acc[i] = make_float4(0.f, 0.f, 0.f, 0.f);

    const int bkr = tid >> 4;          // B loader row 0..15
    const int bn4 = (tid & 15) << 2;   // B loader col

    for (int k0 = 0; k0 < DIM; k0 += 16) {
        #pragma unroll
        for (int t = 0; t < 2; t++) {
            int idx = tid + t * 256;
            int am  = idx >> 2;
            int ak4 = (idx & 3) << 2;
            float4 av = make_float4(0.f, 0.f, 0.f, 0.f);
            if (row0 + am < M)
                av = *(const float4*)(A + (size_t)(row0 + am) * DIM + k0 + ak4);
            As[ak4 + 0][am] = av.x;
            As[ak4 + 1][am] = av.y;
            As[ak4 + 2][am] = av.z;
            As[ak4 + 3][am] = av.w;
        }
        *(float4*)&Bs[bkr][bn4] =
            *(const float4*)(B + (size_t)(k0 + bkr) * DIM + col0 + bn4);
        __syncthreads();

        #pragma unroll
        for (int kk = 0; kk < 16; kk++) {
            float4 bv = *(const float4*)&Bs[kk][tn << 2];
            float4 a0 = *(const float4*)&As[kk][tm * 8];
            float4 a1 = *(const float4*)&As[kk][tm * 8 + 4];
            float av[8] = {a0.x, a0.y, a0.z, a0.w, a1.x, a1.y, a1.z, a1.w};
            #pragma unroll
            for (int i = 0; i < 8; i++) {
                acc[i].x += av[i] * bv.x;
                acc[i].y += av[i] * bv.y;
                acc[i].z += av[i] * bv.z;
                acc[i].w += av[i] * bv.w;
            }
        }
        __syncthreads();
    }

    float4 bb = *(const float4*)(bias + col0 + (tn << 2));
    #pragma unroll
    for (int i = 0; i < 8; i++) {
        int row = row0 + tm * 8 + i;
        if (row < M) {
            float4 o;
            o.x = acc[i].x + bb.x;
            o.y = acc[i].y + bb.y;
            o.z = acc[i].z + bb.z;
            o.w = acc[i].w + bb.w;
            *(float4*)(g_embW + (size_t)row * DIM + col0 + (tn << 2)) = o;
        }
    }
}

// ---------------- kernel 2: persistent RNN recurrence -----------------------
// 128 CTAs: blockIdx = rg*8 + cg.  rg in [0,16): 16 batch rows.  cg in [0,8): 64 cols.
// Row-groups are independent; within a group, 8 CTAs sync via per-CTA counters.
// NO __syncthreads in the step loop: each warp stages its own 4 h-rows privately,
// publishes with per-thread red.release, acquires with relaxed-poll + acq_rel fence.
__global__ __launch_bounds__(256, 1) void rnn_recur(
    const int*   __restrict__ x,    // [256][512] tokens
    const float* __restrict__ Wh)   // [512][512]
{
    extern __shared__ float smem[];
    float* whs = smem;                         // [512][64] Wh column slice
    // per-warp h buffers after whs

    const int tid  = threadIdx.x;
    const int warp = tid >> 5;
    const int lane = tid & 31;
    const int bid  = blockIdx.x;
    const int rg   = bid >> 3;
    const int cg   = bid & 7;
    const int col0 = cg * 64;
    const int row0 = rg * 16;

    // load Wh slice into SMEM once (coalesced)
    for (int i = tid; i < 512 * 16; i += 256) {
        int d  = i >> 4;
        int j4 = (i & 15) << 2;
        *(float4*)&whs[d * 64 + j4] =
            *(const float4*)(Wh + (size_t)d * DIM + col0 + j4);
    }

    // warp -> 4 rows x 32 cols; thread -> 1 row x 4 cols, full K=512
    const int rq   = warp & 3;                  // row quad 0..3
    const int ch   = warp >> 2;                 // col half 0..1
    const int c4   = (ch << 3) + (lane & 7);    // 0..15 (4-col group)
    const int rloc = lane >> 3;                 // 0..3 within quad
    const int r    = (rq << 2) + rloc;          // 0..15
    const int grow = row0 + r;
    const int* xrow = x + (size_t)grow * SEQL;

    float* h_w = smem + 512 * 64 + warp * HWARP;       // this warp's 4 rows
    const float4* hrow4 = (const float4*)&h_w[rloc * HROW];
    const float4* w4    = ((const float4*)whs) + c4;   // stride 16 float4 per d

    unsigned* myflag = &g_flags[rg][cg];
    const unsigned base = ld_relaxed(myflag);   // replay-safe monotonic base
    const unsigned* pollflag = &g_flags[rg][lane & 7];

    __syncthreads();   // whs + base ready (only barrier outside the loop)

    for (int l = 0; l < SEQL; l++) {
        // prefetch xin early (independent of sync / h)
        int token = __ldg(xrow + l);
        float4 xin = __ldg((const float4*)(g_embW + (size_t)token * DIM + col0 + (c4 << 2)));

        float4 acc = make_float4(0.f, 0.f, 0.f, 0.f);

        if (l > 0) {
            // ---- acquire: all 8 sibling CTAs finished step l-1 ----
            unsigned target = base + (unsigned)l * 256u;
            while ((int)(ld_relaxed(pollflag) - target) < 0) { }
            __syncwarp();
            fence_acq_rel_gpu();   // per-lane acquire ordering for the h loads

            // ---- stage this warp's 4 h rows (8KB) from L2 into private smem ----
            const float* hsrc = g_h + (size_t)(l & 1) * (BATCH * DIM)
                                    + (size_t)(row0 + (rq << 2)) * DIM;
            #pragma unroll
            for (int j = 0; j < 4; j++) {
                const float4* src = (const float4*)(hsrc + j * DIM);
                float4 v0 = __ldcg(src + lane);
                float4 v1 = __ldcg(src + lane + 32);
                float4 v2 = __ldcg(src + lane + 64);
                float4 v3 = __ldcg(src + lane + 96);
                float4* dst = (float4*)&h_w[j * HROW];
                dst[lane]      = v0;
                dst[lane + 32] = v1;
                dst[lane + 64] = v2;
                dst[lane + 96] = v3;
            }
            __syncwarp();

            // ---- h @ Wh slice: 2048 FMAs/thread ----
            #pragma unroll 4
            for (int d4 = 0; d4 < 128; d4++) {
                float4 hv = hrow4[d4];
                float4 w0 = w4[(d4 * 4 + 0) * 16];
                float4 w1 = w4[(d4 * 4 + 1) * 16];
                float4 w2 = w4[(d4 * 4 + 2) * 16];
                float4 w3 = w4[(d4 * 4 + 3) * 16];
                acc.x += hv.x * w0.x; acc.y += hv.x * w0.y; acc.z += hv.x * w0.z; acc.w += hv.x * w0.w;
                acc.x += hv.y * w1.x; acc.y += hv.y * w1.y; acc.z += hv.y * w1.z; acc.w += hv.y * w1.w;
                acc.x += hv.z * w2.x; acc.y += hv.z * w2.y; acc.z += hv.z * w2.z; acc.w += hv.z * w2.w;
                acc.x += hv.w * w3.x; acc.y += hv.w * w3.y; acc.z += hv.w * w3.z; acc.w += hv.w * w3.w;
            }
        }

        float4 hn;
        hn.x = tanhf(acc.x + xin.x);
        hn.y = tanhf(acc.y + xin.y);
        hn.z = tanhf(acc.z + xin.z);
        hn.w = tanhf(acc.w + xin.w);

        __stcg((float4*)(g_h + (size_t)((l + 1) & 1) * (BATCH * DIM)
                         + (size_t)grow * DIM + col0 + (c4 << 2)), hn);

        // ---- release: this thread's store is published; count arrival ----
        red_release_add(myflag, 1u);
    }
    // flags end at base + 256*512 in every CTA: next launch re-reads as new base
}

// ---------------- kernel 3: logits + softmax --------------------------------
// final h is in g_h[0] (step 511 writes buffer (511+1)&1 == 0).
__global__ __launch_bounds__(256) void softmax_kernel(
    const float* __restrict__ Wd,   // [512][20]
    const float* __restrict__ bd,   // [20]
    float* __restrict__ out)        // [256][20]
{
    int b    = blockIdx.x * 8 + (threadIdx.x >> 5);
    int lane = threadIdx.x & 31;
    if (b >= BATCH) return;

    const float* h = g_h + (size_t)b * DIM;

    float acc[NCLS];
    #pragma unroll
    for (int c = 0; c < NCLS; c++) acc[c] = 0.f;

    for (int d = lane; d < DIM; d += 32) {
        float hv = __ldcg(h + d);
        #pragma unroll
        for (int c = 0; c < NCLS; c++)
            acc[c] += hv * Wd[d * NCLS + c];
    }
    #pragma unroll
    for (int c = 0; c < NCLS; c++) {
        #pragma unroll
        for (int off = 16; off > 0; off >>= 1)
            acc[c] += __shfl_xor_sync(0xFFFFFFFFu, acc[c], off);
    }
    if (lane == 0) {
        float logit[NCLS];
        float m = -1e30f;
        #pragma unroll
        for (int c = 0; c < NCLS; c++) {
            logit[c] = acc[c] + bd[c];
            m = fmaxf(m, logit[c]);
        }
        float s = 0.f;
        #pragma unroll
        for (int c = 0; c < NCLS; c++) {
            logit[c] = expf(logit[c] - m);
            s += logit[c];
        }
        float inv = 1.0f / s;
        #pragma unroll
        for (int c = 0; c < NCLS; c++)
            out[b * NCLS + c] = logit[c] * inv;
    }
}

// ---------------- launch ----------------------------------------------------
extern "C" void kernel_launch(void* const* d_in, const int* in_sizes, int n_in,
                              void* d_out, int out_size)
{
    const int*   x   = (const int*)  d_in[0];
    const float* emb = (const float*)d_in[1];
    const float* Wx  = (const float*)d_in[2];
    const float* Wh  = (const float*)d_in[3];
    const float* b   = (const float*)d_in[4];
    const float* Wd  = (const float*)d_in[5];
    const float* bd  = (const float*)d_in[6];
    float* out = (float*)d_out;

    // 1) embW = emb @ Wx + b
    embw_gemm<<<dim3(DIM / 64, (VOCAB + 127) / 128), 256>>>(emb, Wx, b, VOCAB);

    // 2) persistent recurrence (128 CTAs, ~197KB dynamic smem, all resident)
    cudaFuncSetAttribute(rnn_recur, cudaFuncAttributeMaxDynamicSharedMemorySize,
                         RNN_SMEM_BYTES);
    rnn_recur<<<128, 256, RNN_SMEM_BYTES>>>(x, Wh);

    // 3) logits + softmax
    softmax_kernel<<<(BATCH + 7) / 8, 256>>>(Wd, bd, out);
}

// round 6
// speedup vs baseline: 2.1696x; 2.1696x over previous
#include <cuda_runtime.h>
#include <cuda_bf16.h>
#include <math.h>

// Problem constants
#define VOCAB 50000
#define DIM   512
#define SEQL  512
#define BATCH 256
#define NCLS  20

// smem layout (floats): wt[64][516] transposed Wh slice, hs[16][516]
#define CSTR  516
#define RNN_SMEM_FLOATS ((64 + 16) * CSTR)
#define RNN_SMEM_BYTES  (RNN_SMEM_FLOATS * 4)   // 165,120 B

typedef unsigned long long ull;

// ---------------- device scratch (no runtime alloc allowed) ----------------
__device__ float g_embW[(size_t)VOCAB * DIM];       // emb @ Wx + b, ~100 MB
__device__ float g_h[2 * BATCH * DIM];              // ping-pong hidden state
__device__ unsigned g_flags[16][32];                // per-CTA step flags (8 used/group)

// strong acquire/release flag ops (R3-proven protocol)
__device__ __forceinline__ unsigned ldflag_acq(const unsigned* p) {
    unsigned v;
    asm volatile("ld.acquire.gpu.global.u32 %0, [%1];" : "=r"(v) : "l"(p) : "memory");
    return v;
}
__device__ __forceinline__ void stflag_rel(unsigned* p, unsigned v) {
    asm volatile("st.release.gpu.global.u32 [%0], %1;" :: "l"(p), "r"(v) : "memory");
}

// packed fp32x2 math (sm_103a native; ptxas never auto-generates these)
__device__ __forceinline__ ull fma2(ull a, ull b, ull c) {
    ull d;
    asm("fma.rn.f32x2 %0, %1, %2, %3;" : "=l"(d) : "l"(a), "l"(b), "l"(c));
    return d;
}
__device__ __forceinline__ ull add2(ull a, ull b) {
    ull d;
    asm("add.rn.f32x2 %0, %1, %2;" : "=l"(d) : "l"(a), "l"(b));
    return d;
}
__device__ __forceinline__ ull shflx64(ull v, int m) {
    unsigned lo = (unsigned)v, hi = (unsigned)(v >> 32);
    lo = __shfl_xor_sync(0xffffffffu, lo, m);
    hi = __shfl_xor_sync(0xffffffffu, hi, m);
    return ((ull)hi << 32) | (ull)lo;
}

// ---------------- kernel 1: embW = emb @ Wx + b  (fp32 tiled GEMM) ----------
__global__ __launch_bounds__(256) void embw_gemm(
    const float* __restrict__ A,    // emb [M][512]
    const float* __restrict__ B,    // Wx  [512][512]
    const float* __restrict__ bias, // b [512]
    int M)
{
    __shared__ float As[16][132];
    __shared__ float Bs[16][64];

    const int tid  = threadIdx.x;
    const int row0 = blockIdx.y * 128;
    const int col0 = blockIdx.x * 64;
    const int tm = tid >> 4;
    const int tn = tid & 15;

    float4 acc[8];
    #pragma unroll
    for (int i = 0; i < 8; i++) acc[i] = make_float4(0.f, 0.f, 0.f, 0.f);

    const int bkr = tid >> 4;
    const int bn4 = (tid & 15) << 2;

    for (int k0 = 0; k0 < DIM; k0 += 16) {
        #pragma unroll
        for (int t = 0; t < 2; t++) {
            int idx = tid + t * 256;
            int am  = idx >> 2;
            int ak4 = (idx & 3) << 2;
            float4 av = make_float4(0.f, 0.f, 0.f, 0.f);
            if (row0 + am < M)
                av = *(const float4*)(A + (size_t)(row0 + am) * DIM + k0 + ak4);
            As[ak4 + 0][am] = av.x;
            As[ak4 + 1][am] = av.y;
            As[ak4 + 2][am] = av.z;
            As[ak4 + 3][am] = av.w;
        }
        *(float4*)&Bs[bkr][bn4] =
            *(const float4*)(B + (size_t)(k0 + bkr) * DIM + col0 + bn4);
        __syncthreads();

        #pragma unroll
        for (int kk = 0; kk < 16; kk++) {
            float4 bv = *(const float4*)&Bs[kk][tn << 2];
            float4 a0 = *(const float4*)&As[kk][tm * 8];
            float4 a1 = *(const float4*)&As[kk][tm * 8 + 4];
            float av[8] = {a0.x, a0.y, a0.z, a0.w, a1.x, a1.y, a1.z, a1.w};
            #pragma unroll
            for (int i = 0; i < 8; i++) {
                acc[i].x += av[i] * bv.x;
                acc[i].y += av[i] * bv.y;
                acc[i].z += av[i] * bv.z;
                acc[i].w += av[i] * bv.w;
            }
        }
        __syncthreads();
    }

    float4 bb = *(const float4*)(bias + col0 + (tn << 2));
    #pragma unroll
    for (int i = 0; i < 8; i++) {
        int row = row0 + tm * 8 + i;
        if (row < M) {
            float4 o;
            o.x = acc[i].x + bb.x;
            o.y = acc[i].y + bb.y;
            o.z = acc[i].z + bb.z;
            o.w = acc[i].w + bb.w;
            *(float4*)(g_embW + (size_t)row * DIM + col0 + (tn << 2)) = o;
        }
    }
}

// ---------------- kernel 2: persistent RNN recurrence -----------------------
// 128 CTAs: blockIdx = rg*8 + cg.  rg in [0,16): 16 batch rows.  cg in [0,8): 64 cols.
// Thread tile: 8 rows x 4 cols x 64 K-values (kq in [0,8) splits K).
// Wh slice TRANSPOSED in smem -> fp32x2 FMA over K pairs; kq-skewed d to kill
// bank conflicts; 3-round shuffle reduce-scatter for the K-split partials.
__global__ __launch_bounds__(256, 1) void rnn_recur(
    const int*   __restrict__ x,    // [256][512] tokens
    const float* __restrict__ Wh)   // [512][512]
{
    extern __shared__ float smem[];
    float* wt = smem;                 // [64][CSTR] transposed: wt[c][d]
    float* hs = smem + 64 * CSTR;     // [16][CSTR]

    const int tid  = threadIdx.x;
    const int warp = tid >> 5;
    const int lane = tid & 31;
    const int rg   = blockIdx.x >> 3;
    const int cg   = blockIdx.x & 7;
    const int col0 = cg * 64;
    const int row0 = rg * 16;

    // one-time transposed load of Wh slice: wt[c][d] = Wh[d][col0+c]
    for (int idx = tid; idx < 512 * 16; idx += 256) {
        int d  = idx >> 4;
        int c4 = (idx & 15) << 2;
        float4 v = *(const float4*)(Wh + (size_t)d * DIM + col0 + c4);
        wt[(c4 + 0) * CSTR + d] = v.x;
        wt[(c4 + 1) * CSTR + d] = v.y;
        wt[(c4 + 2) * CSTR + d] = v.z;
        wt[(c4 + 3) * CSTR + d] = v.w;
    }

    // thread mapping: lane[2:0]=kq, lane[4:3]=cq_lo, warp[1:0]=cq_hi, warp[2]=rq
    const int kq   = lane & 7;                        // K-slice 0..7 (64 d each)
    const int cqlo = lane >> 3;                       // 0..3
    const int rq   = warp >> 2;                       // 0..1 (8 rows each)
    const int cq   = ((warp & 3) << 2) | cqlo;        // 0..15 (4 cols each)
    const int c0   = cq << 2;                         // col in [0,64)
    const int r0   = rq << 3;                         // row in [0,16)

    const int outrow  = row0 + r0 + kq;               // this thread's output row
    const int outcolg = col0 + c0;                    // global col base (4 cols)
    const int* xrow = x + (size_t)outrow * SEQL;

    unsigned* myflag = &g_flags[rg][cg];
    const unsigned base = ldflag_acq(myflag);         // replay-safe monotonic base

    __syncthreads();

    for (int l = 0; l < SEQL; l++) {
        // prefetch xin early (independent of sync / h)
        int token = __ldg(xrow + l);
        float4 xin = __ldg((const float4*)(g_embW + (size_t)token * DIM + outcolg));

        float fin0 = 0.f, fin1 = 0.f, fin2 = 0.f, fin3 = 0.f;

        if (l > 0) {
            // ---- per-group acquire wait (8 producers) ----
            unsigned target = base + (unsigned)l;
            if (lane < 8) {
                const unsigned* f = &g_flags[rg][lane];
                while ((int)(ldflag_acq(f) - target) < 0) { }
            }
            __syncwarp();
            __threadfence();

            // ---- stage 16x512 h block (32KB) from L2, coalesced ----
            const float* hsrc = g_h + (size_t)(l & 1) * (BATCH * DIM) + (size_t)row0 * DIM;
            #pragma unroll
            for (int k = 0; k < 8; k++) {
                int idx = tid + (k << 8);
                int row = idx >> 7;
                int cc4 = idx & 127;
                float4 v = __ldcg((const float4*)(hsrc + row * DIM) + cc4);
                *(float4*)(hs + row * CSTR + (cc4 << 2)) = v;
            }
            __syncthreads();

            // ---- h @ Wh: 8 rows x 4 cols x 64 K, fp32x2 packed over K ----
            ull acc[8][4];
            #pragma unroll
            for (int j = 0; j < 8; j++)
                #pragma unroll
                for (int i = 0; i < 4; i++) acc[j][i] = 0ull;

            #pragma unroll 4
            for (int dq = 0; dq < 16; dq++) {
                // kq-skewed float4 index: banks 4*(kq+dq) mod 32 -> conflict-free
                int di = (kq << 4) + ((dq + kq) & 15);
                int db = di << 2;   // float offset
                ulonglong2 wv[4];
                #pragma unroll
                for (int i = 0; i < 4; i++)
                    wv[i] = *(const ulonglong2*)(wt + (c0 + i) * CSTR + db);
                #pragma unroll
                for (int j = 0; j < 8; j++) {
                    ulonglong2 hv = *(const ulonglong2*)(hs + (r0 + j) * CSTR + db);
                    #pragma unroll
                    for (int i = 0; i < 4; i++) {
                        acc[j][i] = fma2(hv.x, wv[i].x, acc[j][i]);
                        acc[j][i] = fma2(hv.y, wv[i].y, acc[j][i]);
                    }
                }
            }

            // ---- reduce-scatter over 8 kq lanes (rounds xor 4,2,1) ----
            // retained j converges to j == kq  ->  output row = r0 + kq
            float fin[4];
            #pragma unroll
            for (int i = 0; i < 4; i++) {
                #pragma unroll
                for (int jj = 0; jj < 4; jj++) {
                    ull s = (kq & 4) ? acc[jj][i] : acc[jj + 4][i];
                    ull r = shflx64(s, 4);
                    ull kkeep = (kq & 4) ? acc[jj + 4][i] : acc[jj][i];
                    acc[jj][i] = add2(kkeep, r);
                }
                #pragma unroll
                for (int jj = 0; jj < 2; jj++) {
                    ull s = (kq & 2) ? acc[jj][i] : acc[jj + 2][i];
                    ull r = shflx64(s, 2);
                    ull kkeep = (kq & 2) ? acc[jj + 2][i] : acc[jj][i];
                    acc[jj][i] = add2(kkeep, r);
                }
                {
                    ull s = (kq & 1) ? acc[0][i] : acc[1][i];
                    ull r = shflx64(s, 1);
                    ull kkeep = (kq & 1) ? acc[1][i] : acc[0][i];
                    ull f = add2(kkeep, r);
                    float2 ff = *(float2*)&f;
                    fin[i] = ff.x + ff.y;    // horizontal add of the K pair streams
                }
            }
            fin0 = fin[0]; fin1 = fin[1]; fin2 = fin[2]; fin3 = fin[3];
        }

        float4 hn;
        hn.x = tanhf(fin0 + xin.x);
        hn.y = tanhf(fin1 + xin.y);
        hn.z = tanhf(fin2 + xin.z);
        hn.w = tanhf(fin3 + xin.w);

        __stcg((float4*)(g_h + (size_t)((l + 1) & 1) * (BATCH * DIM)
                         + (size_t)outrow * DIM + outcolg), hn);

        // ---- release: make h-stores GPU-visible, then publish step flag ----
        __threadfence();
        __syncthreads();
        if (tid == 0) stflag_rel(myflag, base + (unsigned)(l + 1));
    }
    // flags end at base+512: next launch re-reads as its new base (no reset)
}

// ---------------- kernel 3: logits + softmax --------------------------------
__global__ __launch_bounds__(256) void softmax_kernel(
    const float* __restrict__ Wd,   // [512][20]
    const float* __restrict__ bd,   // [20]
    float* __restrict__ out)        // [256][20]
{
    int b    = blockIdx.x * 8 + (threadIdx.x >> 5);
    int lane = threadIdx.x & 31;
    if (b >= BATCH) return;

    const float* h = g_h + (size_t)b * DIM;

    float acc[NCLS];
    #pragma unroll
    for (int c = 0; c < NCLS; c++) acc[c] = 0.f;

    for (int d = lane; d < DIM; d += 32) {
        float hv = __ldcg(h + d);
        #pragma unroll
        for (int c = 0; c < NCLS; c++)
            acc[c] += hv * Wd[d * NCLS + c];
    }
    #pragma unroll
    for (int c = 0; c < NCLS; c++) {
        #pragma unroll
        for (int off = 16; off > 0; off >>= 1)
            acc[c] += __shfl_xor_sync(0xFFFFFFFFu, acc[c], off);
    }
    if (lane == 0) {
        float logit[NCLS];
        float m = -1e30f;
        #pragma unroll
        for (int c = 0; c < NCLS; c++) {
            logit[c] = acc[c] + bd[c];
            m = fmaxf(m, logit[c]);
        }
        float s = 0.f;
        #pragma unroll
        for (int c = 0; c < NCLS; c++) {
            logit[c] = expf(logit[c] - m);
            s += logit[c];
        }
        float inv = 1.0f / s;
        #pragma unroll
        for (int c = 0; c < NCLS; c++)
            out[b * NCLS + c] = logit[c] * inv;
    }
}

// ---------------- launch ----------------------------------------------------
extern "C" void kernel_launch(void* const* d_in, const int* in_sizes, int n_in,
                              void* d_out, int out_size)
{
    const int*   x   = (const int*)  d_in[0];
    const float* emb = (const float*)d_in[1];
    const float* Wx  = (const float*)d_in[2];
    const float* Wh  = (const float*)d_in[3];
    const float* b   = (const float*)d_in[4];
    const float* Wd  = (const float*)d_in[5];
    const float* bd  = (const float*)d_in[6];
    float* out = (float*)d_out;

    // 1) embW = emb @ Wx + b
    embw_gemm<<<dim3(DIM / 64, (VOCAB + 127) / 128), 256>>>(emb, Wx, b, VOCAB);

    // 2) persistent recurrence (128 CTAs, ~165KB dynamic smem, all resident)
    cudaFuncSetAttribute(rnn_recur, cudaFuncAttributeMaxDynamicSharedMemorySize,
                         RNN_SMEM_BYTES);
    rnn_recur<<<128, 256, RNN_SMEM_BYTES>>>(x, Wh);

    // 3) logits + softmax
    softmax_kernel<<<(BATCH + 7) / 8, 256>>>(Wd, bd, out);
}

// round 7
// speedup vs baseline: 2.3651x; 1.0901x over previous
#include <cuda_runtime.h>
#include <cuda_bf16.h>
#include <math.h>

// Problem constants
#define VOCAB 50000
#define DIM   512
#define SEQL  512
#define BATCH 256
#define NCLS  20

// smem layout (floats): wt[64][516] rotated+transposed Wh slice, hs[16][516]
#define CSTR  516
#define RNN_SMEM_FLOATS ((64 + 16) * CSTR)
#define RNN_SMEM_BYTES  (RNN_SMEM_FLOATS * 4)   // 165,120 B
#define RNN_THREADS 128

typedef unsigned long long ull;

// ---------------- device scratch (no runtime alloc allowed) ----------------
__device__ float g_embW[(size_t)VOCAB * DIM];       // emb @ Wx + b, ~100 MB
__device__ float g_h[2 * BATCH * DIM];              // ping-pong hidden state
__device__ unsigned g_flags[16][32];                // per-CTA step flags (8 used/group)

// strong acquire/release flag ops (proven protocol)
__device__ __forceinline__ unsigned ldflag_acq(const unsigned* p) {
    unsigned v;
    asm volatile("ld.acquire.gpu.global.u32 %0, [%1];" : "=r"(v) : "l"(p) : "memory");
    return v;
}
__device__ __forceinline__ void stflag_rel(unsigned* p, unsigned v) {
    asm volatile("st.release.gpu.global.u32 [%0], %1;" :: "l"(p), "r"(v) : "memory");
}

// packed fp32x2 math (sm_103a native; ptxas never auto-generates these)
__device__ __forceinline__ ull fma2(ull a, ull b, ull c) {
    ull d;
    asm("fma.rn.f32x2 %0, %1, %2, %3;" : "=l"(d) : "l"(a), "l"(b), "l"(c));
    return d;
}
__device__ __forceinline__ ull add2(ull a, ull b) {
    ull d;
    asm("add.rn.f32x2 %0, %1, %2;" : "=l"(d) : "l"(a), "l"(b));
    return d;
}
__device__ __forceinline__ ull shflx64(ull v, int m) {
    unsigned lo = (unsigned)v, hi = (unsigned)(v >> 32);
    lo = __shfl_xor_sync(0xffffffffu, lo, m);
    hi = __shfl_xor_sync(0xffffffffu, hi, m);
    return ((ull)hi << 32) | (ull)lo;
}

// ---------------- kernel 1: embW = emb @ Wx + b  (fp32 tiled GEMM) ----------
__global__ __launch_bounds__(256) void embw_gemm(
    const float* __restrict__ A,    // emb [M][512]
    const float* __restrict__ B,    // Wx  [512][512]
    const float* __restrict__ bias, // b [512]
    int M)
{
    __shared__ float As[16][132];
    __shared__ float Bs[16][64];

    const int tid  = threadIdx.x;
    const int row0 = blockIdx.y * 128;
    const int col0 = blockIdx.x * 64;
    const int tm = tid >> 4;
    const int tn = tid & 15;

    float4 acc[8];
    #pragma unroll
    for (int i = 0; i < 8; i++) acc[i] = make_float4(0.f, 0.f, 0.f, 0.f);

    const int bkr = tid >> 4;
    const int bn4 = (tid & 15) << 2;

    for (int k0 = 0; k0 < DIM; k0 += 16) {
        #pragma unroll
        for (int t = 0; t < 2; t++) {
            int idx = tid + t * 256;
            int am  = idx >> 2;
            int ak4 = (idx & 3) << 2;
            float4 av = make_float4(0.f, 0.f, 0.f, 0.f);
            if (row0 + am < M)
                av = *(const float4*)(A + (size_t)(row0 + am) * DIM + k0 + ak4);
            As[ak4 + 0][am] = av.x;
            As[ak4 + 1][am] = av.y;
            As[ak4 + 2][am] = av.z;
            As[ak4 + 3][am] = av.w;
        }
        *(float4*)&Bs[bkr][bn4] =
            *(const float4*)(B + (size_t)(k0 + bkr) * DIM + col0 + bn4);
        __syncthreads();

        #pragma unroll
        for (int kk = 0; kk < 16; kk++) {
            float4 bv = *(const float4*)&Bs[kk][tn << 2];
            float4 a0 = *(const float4*)&As[kk][tm * 8];
            float4 a1 = *(const float4*)&As[kk][tm * 8 + 4];
            float av[8] = {a0.x, a0.y, a0.z, a0.w, a1.x, a1.y, a1.z, a1.w};
            #pragma unroll
            for (int i = 0; i < 8; i++) {
                acc[i].x += av[i] * bv.x;
                acc[i].y += av[i] * bv.y;
                acc[i].z += av[i] * bv.z;
                acc[i].w += av[i] * bv.w;
            }
        }
        __syncthreads();
    }

    float4 bb = *(const float4*)(bias + col0 + (tn << 2));
    #pragma unroll
    for (int i = 0; i < 8; i++) {
        int row = row0 + tm * 8 + i;
        if (row < M) {
            float4 o;
            o.x = acc[i].x + bb.x;
            o.y = acc[i].y + bb.y;
            o.z = acc[i].z + bb.z;
            o.w = acc[i].w + bb.w;
            *(float4*)(g_embW + (size_t)row * DIM + col0 + (tn << 2)) = o;
        }
    }
}

// ---------------- kernel 2: persistent RNN recurrence -----------------------
// 128 CTAs: blockIdx = rg*8 + cg.  rg in [0,16): 16 batch rows.  cg in [0,8): 64 cols.
// 128 threads/CTA.  Thread tile: 8 rows x 8 cols x 64 K (kq in [0,8) splits K).
// Lane map: lane[2:0]=kq, lane[4:3]=cqlo; warp bit0=cqhi, bit1=rq.
// wt stored transposed with per-cq float4 rotation (+2*cq mod 128): wv loads
// conflict-free per 8-lane phase.  hv keeps kq-skew (+broadcast over cqlo).
__global__ __launch_bounds__(RNN_THREADS, 1) void rnn_recur(
    const int*   __restrict__ x,    // [256][512] tokens
    const float* __restrict__ Wh)   // [512][512]
{
    extern __shared__ float smem[];
    float* wt = smem;                 // [64][CSTR] rotated transpose: see below
    float* hs = smem + 64 * CSTR;     // [16][CSTR] linear

    const int tid  = threadIdx.x;
    const int warp = tid >> 5;
    const int lane = tid & 31;
    const int rg   = blockIdx.x >> 3;
    const int cg   = blockIdx.x & 7;
    const int col0 = cg * 64;
    const int row0 = rg * 16;

    // one-time rotated transposed load: wt[c][ ((d>>2 + 2*(c>>3)) & 127)*4 + (d&3) ] = Wh[d][col0+c]
    for (int idx = tid; idx < 512 * 16; idx += RNN_THREADS) {
        int d  = idx >> 4;
        int c4 = (idx & 15) << 2;
        int f  = d >> 2;
        int dl = d & 3;
        float4 v = *(const float4*)(Wh + (size_t)d * DIM + col0 + c4);
        float vv[4] = {v.x, v.y, v.z, v.w};
        #pragma unroll
        for (int q = 0; q < 4; q++) {
            int c = c4 + q;
            int p = (f + 2 * (c >> 3)) & 127;
            wt[c * CSTR + (p << 2) + dl] = vv[q];
        }
    }

    // thread mapping
    const int kq   = lane & 7;                 // K-slice 0..7 (64 d each)
    const int cqlo = lane >> 3;                // 0..3
    const int cq   = ((warp & 1) << 2) | cqlo; // 0..7  -> 8 cols each
    const int rq   = warp >> 1;                // 0..1  -> 8 rows each
    const int c0   = cq << 3;                  // col in [0,64)
    const int r0   = rq << 3;                  // row in [0,16)
    const int rot  = 2 * cq;                   // wt rotation for this thread's cols

    const int outrow  = row0 + r0 + kq;        // this thread's output row
    const int outcolg = col0 + c0;             // global col base (8 cols)
    const int* xrow = x + (size_t)outrow * SEQL;

    unsigned* myflag = &g_flags[rg][cg];
    const unsigned base = ldflag_acq(myflag);  // replay-safe monotonic base

    __syncthreads();

    for (int l = 0; l < SEQL; l++) {
        // prefetch xin early (independent of sync / h)
        int token = __ldg(xrow + l);
        const float* embrow = g_embW + (size_t)token * DIM + outcolg;
        float4 xin0 = __ldg((const float4*)embrow);
        float4 xin1 = __ldg((const float4*)(embrow + 4));

        float fin[8];
        #pragma unroll
        for (int i = 0; i < 8; i++) fin[i] = 0.f;

        if (l > 0) {
            // ---- per-group acquire wait (8 producers) ----
            unsigned target = base + (unsigned)l;
            if (lane < 8) {
                const unsigned* f = &g_flags[rg][lane];
                while ((int)(ldflag_acq(f) - target) < 0) { }
            }
            __syncwarp();
            __threadfence();

            // ---- stage 16x512 h block (32KB) from L2, coalesced ----
            const float* hsrc = g_h + (size_t)(l & 1) * (BATCH * DIM) + (size_t)row0 * DIM;
            #pragma unroll
            for (int k = 0; k < 16; k++) {
                int idx = tid + (k << 7);         // 0..2047 float4
                int row = idx >> 7;
                int cc4 = idx & 127;
                float4 v = __ldcg((const float4*)(hsrc + row * DIM) + cc4);
                *(float4*)(hs + row * CSTR + (cc4 << 2)) = v;
            }
            __syncthreads();

            // ---- h @ Wh: 8 rows x 8 cols x 64 K, fp32x2 packed over K ----
            ull acc[8][8];
            #pragma unroll
            for (int j = 0; j < 8; j++)
                #pragma unroll
                for (int i = 0; i < 8; i++) acc[j][i] = 0ull;

            const float* wbase = wt + c0 * CSTR;

            #pragma unroll 4
            for (int dq = 0; dq < 16; dq++) {
                int s   = (dq + kq) & 15;
                int di  = (kq << 4) + s;           // natural float4 index (hv)
                int dr  = (di + rot) & 127;        // rotated float4 index (wv)
                int dbh = di << 2;
                int dbw = dr << 2;

                ulonglong2 wv[8];
                #pragma unroll
                for (int i = 0; i < 8; i++)
                    wv[i] = *(const ulonglong2*)(wbase + i * CSTR + dbw);

                #pragma unroll
                for (int j = 0; j < 8; j++) {
                    ulonglong2 hv = *(const ulonglong2*)(hs + (r0 + j) * CSTR + dbh);
                    #pragma unroll
                    for (int i = 0; i < 8; i++) {
                        acc[j][i] = fma2(hv.x, wv[i].x, acc[j][i]);
                        acc[j][i] = fma2(hv.y, wv[i].y, acc[j][i]);
                    }
                }
            }

            // ---- reduce-scatter over 8 kq lanes (rounds xor 4,2,1) ----
            // retained j converges to j == kq  ->  output row = r0 + kq
            #pragma unroll
            for (int i = 0; i < 8; i++) {
                #pragma unroll
                for (int jj = 0; jj < 4; jj++) {
                    ull s = (kq & 4) ? acc[jj][i] : acc[jj + 4][i];
                    ull r = shflx64(s, 4);
                    ull kkeep = (kq & 4) ? acc[jj + 4][i] : acc[jj][i];
                    acc[jj][i] = add2(kkeep, r);
                }
                #pragma unroll
                for (int jj = 0; jj < 2; jj++) {
                    ull s = (kq & 2) ? acc[jj][i] : acc[jj + 2][i];
                    ull r = shflx64(s, 2);
                    ull kkeep = (kq & 2) ? acc[jj + 2][i] : acc[jj][i];
                    acc[jj][i] = add2(kkeep, r);
                }
                {
                    ull s = (kq & 1) ? acc[0][i] : acc[1][i];
                    ull r = shflx64(s, 1);
                    ull kkeep = (kq & 1) ? acc[1][i] : acc[0][i];
                    ull f = add2(kkeep, r);
                    float2 ff = *(float2*)&f;
                    fin[i] = ff.x + ff.y;    // horizontal add of the K pair streams
                }
            }
        }

        float4 hn0, hn1;
        hn0.x = tanhf(fin[0] + xin0.x);
        hn0.y = tanhf(fin[1] + xin0.y);
        hn0.z = tanhf(fin[2] + xin0.z);
        hn0.w = tanhf(fin[3] + xin0.w);
        hn1.x = tanhf(fin[4] + xin1.x);
        hn1.y = tanhf(fin[5] + xin1.y);
        hn1.z = tanhf(fin[6] + xin1.z);
        hn1.w = tanhf(fin[7] + xin1.w);

        float* hdst = g_h + (size_t)((l + 1) & 1) * (BATCH * DIM)
                          + (size_t)outrow * DIM + outcolg;
        __stcg((float4*)hdst,       hn0);
        __stcg((float4*)(hdst + 4), hn1);

        // ---- release: make h-stores GPU-visible, then publish step flag ----
        __threadfence();
        __syncthreads();
        if (tid == 0) stflag_rel(myflag, base + (unsigned)(l + 1));
    }
    // flags end at base+512: next launch re-reads as its new base (no reset)
}

// ---------------- kernel 3: logits + softmax --------------------------------
__global__ __launch_bounds__(256) void softmax_kernel(
    const float* __restrict__ Wd,   // [512][20]
    const float* __restrict__ bd,   // [20]
    float* __restrict__ out)        // [256][20]
{
    int b    = blockIdx.x * 8 + (threadIdx.x >> 5);
    int lane = threadIdx.x & 31;
    if (b >= BATCH) return;

    const float* h = g_h + (size_t)b * DIM;

    float acc[NCLS];
    #pragma unroll
    for (int c = 0; c < NCLS; c++) acc[c] = 0.f;

    for (int d = lane; d < DIM; d += 32) {
        float hv = __ldcg(h + d);
        #pragma unroll
        for (int c = 0; c < NCLS; c++)
            acc[c] += hv * Wd[d * NCLS + c];
    }
    #pragma unroll
    for (int c = 0; c < NCLS; c++) {
        #pragma unroll
        for (int off = 16; off > 0; off >>= 1)
            acc[c] += __shfl_xor_sync(0xFFFFFFFFu, acc[c], off);
    }
    if (lane == 0) {
        float logit[NCLS];
        float m = -1e30f;
        #pragma unroll
        for (int c = 0; c < NCLS; c++) {
            logit[c] = acc[c] + bd[c];
            m = fmaxf(m, logit[c]);
        }
        float s = 0.f;
        #pragma unroll
        for (int c = 0; c < NCLS; c++) {
            logit[c] = expf(logit[c] - m);
            s += logit[c];
        }
        float inv = 1.0f / s;
        #pragma unroll
        for (int c = 0; c < NCLS; c++)
            out[b * NCLS + c] = logit[c] * inv;
    }
}

// ---------------- launch ----------------------------------------------------
extern "C" void kernel_launch(void* const* d_in, const int* in_sizes, int n_in,
                              void* d_out, int out_size)
{
    const int*   x   = (const int*)  d_in[0];
    const float* emb = (const float*)d_in[1];
    const float* Wx  = (const float*)d_in[2];
    const float* Wh  = (const float*)d_in[3];
    const float* b   = (const float*)d_in[4];
    const float* Wd  = (const float*)d_in[5];
    const float* bd  = (const float*)d_in[6];
    float* out = (float*)d_out;

    // 1) embW = emb @ Wx + b
    embw_gemm<<<dim3(DIM / 64, (VOCAB + 127) / 128), 256>>>(emb, Wx, b, VOCAB);

    // 2) persistent recurrence (128 CTAs x 128 threads, ~165KB smem, all resident)
    cudaFuncSetAttribute(rnn_recur, cudaFuncAttributeMaxDynamicSharedMemorySize,
                         RNN_SMEM_BYTES);
    rnn_recur<<<128, RNN_THREADS, RNN_SMEM_BYTES>>>(x, Wh);

    // 3) logits + softmax
    softmax_kernel<<<(BATCH + 7) / 8, 256>>>(Wd, bd, out);
}